// round 6
// baseline (speedup 1.0000x reference)
#include <cuda_runtime.h>
#include <cstdint>

typedef uint32_t u32;
typedef unsigned long long u64;
#define TPB 256

// ---- smem float-offsets ----
#define F_BIAS 0        // 256
#define F_WGB  256      // 32 (pad to 320)
#define F_WMU  320      // 1024
#define F_WG   1344     // 8192
#define F_SH   9536     // 4096 (s_h frag tile = main A chunk 8)
#define F_VH   13632    // 3*4096 (tf32 V_h frag tiles)
#define F_A0   25920    // 4096
#define F_A1   30016    // 4096
#define F_B0   34112    // 8192
#define F_B1   42304    // 8192
#define F_WH   50496    // 1024
#define SMEM_FLOATS 51520
#define SMEM_BYTES (SMEM_FLOATS*4)   // 206080 B

// Pre-rounded, pre-fragment-formatted weights.
// B-frag layout per 32-k chunk: idx = ((nt*KS + ks)*32 + lane)*2 + i
//   holds W[n = nt*8 + lane/4][k = ks*8 + lane%4 + i*4]
__device__ u32 g_Bm[73728];  // W_m_w: 9 chunks x 32 nt x 4 ks
__device__ u32 g_Bg[8192];   // W_g:   4 nt x 32 ks
__device__ u32 g_Bh[1024];   // W_h:   4 nt x 4 ks
__device__ u32 g_Bmu[1024];  // W_mu:  4 nt x 4 ks

__device__ __forceinline__ u32 rna(float x){u32 u;asm("cvt.rna.tf32.f32 %0,%1;":"=r"(u):"f"(x));return u;}

__global__ void prep(const float* __restrict__ Wm, const float* __restrict__ Wg,
                     const float* __restrict__ Wh, const float* __restrict__ Wmu){
    int i = blockIdx.x*blockDim.x + threadIdx.x;
    if (i < 73728){
        int c=i>>13, r=i&8191, i2=r&1, lane=(r>>1)&31, ks=(r>>6)&3, nt=r>>8;
        g_Bm[i] = rna(Wm[(nt*8+(lane>>2))*288 + c*32 + ks*8 + (lane&3) + i2*4]);
    } else if (i < 81920){
        int p=i-73728, i2=p&1, lane=(p>>1)&31, ksg=(p>>6)&31, n2=p>>11;
        g_Bg[p] = rna(Wg[(n2*8+(lane>>2))*256 + ksg*8 + (lane&3) + i2*4]);
    } else if (i < 82944){
        int p=i-81920, i2=p&1, lane=(p>>1)&31, ks=(p>>6)&3, n2=p>>8;
        g_Bh[p] = rna(Wh[(n2*8+(lane>>2))*32 + ks*8 + (lane&3) + i2*4]);
    } else if (i < 83968){
        int p=i-82944, i2=p&1, lane=(p>>1)&31, ks=(p>>6)&3, n2=p>>8;
        g_Bmu[p] = rna(Wmu[(n2*8+(lane>>2))*32 + ks*8 + (lane&3) + i2*4]);
    }
}

__device__ __forceinline__ void mma8(float* d, const u32* a, u32 b0, u32 b1){
    asm volatile("mma.sync.aligned.m16n8k8.row.col.f32.tf32.tf32.f32 "
        "{%0,%1,%2,%3},{%4,%5,%6,%7},{%8,%9},{%0,%1,%2,%3};"
        : "+f"(d[0]),"+f"(d[1]),"+f"(d[2]),"+f"(d[3])
        : "r"(a[0]),"r"(a[1]),"r"(a[2]),"r"(a[3]),"r"(b0),"r"(b1));
}
__device__ __forceinline__ u32 smem_u32(const void* p){
    u32 a;asm("{ .reg .u64 t; cvta.to.shared.u64 t,%1; cvt.u32.u64 %0,t; }":"=r"(a):"l"(p));return a;}
__device__ __forceinline__ void cpasync16(u32 d, const void* s){
    asm volatile("cp.async.cg.shared.global [%0], [%1], 16;"::"r"(d),"l"(s):"memory");}
#define CP_COMMIT asm volatile("cp.async.commit_group;":::"memory")
#define CP_WAIT(n) asm volatile("cp.async.wait_group %0;"::"n"(n):"memory")
__device__ __forceinline__ float sigm(float x){return 1.f/(1.f+__expf(-x));}

// A-frag SoA layout: idx = ((mt*4+ks)*4 + j)*32 + lane; a_j: j=0:(r=lane/4,c=lane%4)
// j=1:(r+8), j=2:(c+4), j=3:(r+8,c+4). Writer for (rt,c8): lane=(rt&7)*4+(c8&3),
// j=(rt>>3)+((c8&4)?2:0).
#define AFIDX(mt,ks,j) (((mt)*4+(ks))*4+(j))*32

__global__ void __launch_bounds__(TPB,1) gvp_kernel(
    const float* __restrict__ s_g, const float* __restrict__ V_g,
    const float* __restrict__ Wmb, const float* __restrict__ Wgb,
    float* __restrict__ out, int N)
{
    extern __shared__ float smf[];
    u32* smu = (u32*)smf;
    const int t = threadIdx.x, lane = t&31, w = t>>5;
    const int wm = w>>2, wn = w&3;
    const int node0 = blockIdx.x*128;

    // ---- prologue copies ----
    if (t < 64) ((float4*)(smf+F_BIAS))[t] = ((const float4*)Wmb)[t];
    if (t < 32) smf[F_WGB+t] = Wgb[t];
    ((float4*)(smf+F_WMU))[t] = ((const float4*)g_Bmu)[t];
    ((float4*)(smf+F_WH))[t]  = ((const float4*)g_Bh)[t];
    #pragma unroll
    for (int q=0;q<8;q++) ((float4*)(smf+F_WG))[t+256*q] = ((const float4*)g_Bg)[t+256*q];

    // ---- V scatter into 3 component A-frag buffers (A0,A1,B0) ----
    {
        const int cb[3] = {F_A0, F_A1, F_B0};
        #pragma unroll
        for (int q=0;q<12;q++){
            int g = t + 256*q;
            int node = g/24, j = g - node*24;
            float4 v4 = ((const float4*)V_g)[(size_t)node0*24 + g];
            float vv[4] = {v4.x, v4.y, v4.z, v4.w};
            #pragma unroll
            for (int e=0;e<4;e++){
                int f = 4*j+e, v = f/3, c = f-v*3;
                int mt=node>>4, rt=node&15, ks=v>>3, c8=v&7;
                smu[cb[c] + AFIDX(mt,ks,(rt>>3)+((c8&4)?2:0)) + ((rt&7)*4+(c8&3))] = rna(vv[e]);
            }
        }
    }
    __syncthreads();

    // ---- V_h mma: warp w handles mt=w ----
    float vh[3][4][4];
    #pragma unroll
    for(int c=0;c<3;c++)for(int n2=0;n2<4;n2++)for(int e=0;e<4;e++) vh[c][n2][e]=0.f;
    {
        const int cb[3] = {F_A0, F_A1, F_B0};
        #pragma unroll
        for (int c=0;c<3;c++)
        #pragma unroll
        for (int ks=0;ks<4;ks++){
            u32 a[4];
            #pragma unroll
            for (int j=0;j<4;j++) a[j] = smu[cb[c] + AFIDX(w,ks,j) + lane];
            #pragma unroll
            for (int n2=0;n2<4;n2++){
                u64 bb = ((const u64*)(smu+F_WH))[(n2*4+ks)*32+lane];
                mma8(vh[c][n2], a, (u32)bb, (u32)(bb>>32));
            }
        }
    }
    // ---- norm; write s_h + tf32 V_h frag tiles ----
    #pragma unroll
    for (int n2=0;n2<4;n2++)
    #pragma unroll
    for (int e=0;e<4;e++){
        float x=vh[0][n2][e], y=vh[1][n2][e], z=vh[2][n2][e];
        float sh = fmaxf(sqrtf(x*x+y*y+z*z), 1e-4f);
        int rt = (lane>>2) + ((e>>1)<<3);
        int h  = n2*8 + ((lane&3)<<1) + (e&1);
        int idx = AFIDX(w, h>>3, (rt>>3)+((h&4)?2:0)) + ((rt&7)*4+(h&3));
        smu[F_SH + idx]        = rna(sh);
        smu[F_VH + idx]        = rna(x);
        smu[F_VH + 4096 + idx] = rna(y);
        smu[F_VH + 8192 + idx] = rna(z);
    }
    __syncthreads();

    // ---- main GEMM: D[128,256] = A[128,288] x W^T, 9 chunks of K=32 ----
    float acc[4][8][4];
    #pragma unroll
    for(int i=0;i<4;i++)for(int j=0;j<8;j++)for(int e=0;e<4;e++) acc[i][j][e]=0.f;

    const u32 smb = smem_u32(smf);
    const int ar = t>>1, ah = (t&1)*16;
    float4 apre[4];
    #pragma unroll
    for (int e=0;e<4;e++)
        apre[e] = *(const float4*)(s_g + (size_t)(node0+ar)*256 + ah + 4*e);
    #pragma unroll
    for (int q=0;q<8;q++)
        cpasync16(smb + F_B0*4 + (t+256*q)*16, g_Bm + (t+256*q)*4);
    CP_COMMIT;

    for (int c=0;c<9;c++){
        int buf = c&1;
        int aW = buf? F_A1:F_A0, bR = buf? F_B1:F_B0, bW = buf? F_B0:F_B1;
        if (c<8){
            #pragma unroll
            for (int e=0;e<4;e++){
                float vv[4] = {apre[e].x, apre[e].y, apre[e].z, apre[e].w};
                #pragma unroll
                for (int ee=0;ee<4;ee++){
                    int cc = ah + 4*e + ee;
                    int ks = cc>>3, c8 = cc&7;
                    smu[aW + AFIDX(ar>>4,ks,((ar&8)?1:0)+((c8&4)?2:0)) + (((ar&7)<<2)+(c8&3))]
                        = rna(vv[ee]);
                }
            }
        }
        if (c<7){
            #pragma unroll
            for (int e=0;e<4;e++)
                apre[e] = *(const float4*)(s_g + (size_t)(node0+ar)*256 + (c+1)*32 + ah + 4*e);
        }
        if (c<8){
            const u32* src = g_Bm + (c+1)*8192;
            #pragma unroll
            for (int q=0;q<8;q++)
                cpasync16(smb + bW*4 + (t+256*q)*16, src + (t+256*q)*4);
            CP_COMMIT;
            CP_WAIT(1);
        } else {
            CP_WAIT(0);
        }
        __syncthreads();
        const int aF = (c==8)? F_SH : aW;
        // NOTE: chunk c's B lives in the buffer cp.async'd one iteration earlier
        const int bF = (c==0)? F_B0 : bR;
        #pragma unroll
        for (int ks=0;ks<4;ks++){
            u32 a[4][4];
            #pragma unroll
            for (int i=0;i<4;i++)
                #pragma unroll
                for (int j=0;j<4;j++)
                    a[i][j] = smu[aF + AFIDX(wm*4+i,ks,j) + lane];
            #pragma unroll
            for (int j2=0;j2<8;j2++){
                u64 bb = ((const u64*)(smu+bF))[((wn*8+j2)*4+ks)*32+lane];
                #pragma unroll
                for (int i=0;i<4;i++)
                    mma8(acc[i][j2], a[i], (u32)bb, (u32)(bb>>32));
            }
        }
        __syncthreads();
    }

    // ---- epilogue: bias + relu store; sigma -> gate frag buffers -> gate mma ----
    float2 bi[8];
    #pragma unroll
    for (int j2=0;j2<8;j2++)
        bi[j2] = *(const float2*)(smf + F_BIAS + wn*64 + j2*8 + ((lane&3)<<1));
    #pragma unroll
    for (int i=0;i<4;i++)
    #pragma unroll
    for (int j2=0;j2<8;j2++){
        int col = wn*64 + j2*8 + ((lane&3)<<1);
        int nA = node0 + wm*64 + i*16 + (lane>>2);
        float2 v0 = {fmaxf(acc[i][j2][0]+bi[j2].x,0.f), fmaxf(acc[i][j2][1]+bi[j2].y,0.f)};
        float2 v1 = {fmaxf(acc[i][j2][2]+bi[j2].x,0.f), fmaxf(acc[i][j2][3]+bi[j2].y,0.f)};
        *(float2*)(out + (size_t)nA*256 + col) = v0;
        *(float2*)(out + (size_t)(nA+8)*256 + col) = v1;
    }

    float gacc[4][4];
    #pragma unroll
    for(int n2=0;n2<4;n2++)for(int e=0;e<4;e++) gacc[n2][e]=0.f;
    const int gb[4] = {F_A0, F_A1, F_B0, F_B0+4096};
    for (int r=0;r<2;r++){
        __syncthreads();
        #pragma unroll
        for (int i=0;i<4;i++)
        #pragma unroll
        for (int jj=0;jj<4;jj++){
            int j2 = r*4+jj;
            #pragma unroll
            for (int e=0;e<4;e++){
                float sv = sigm(acc[i][j2][e] + ((e&1)? bi[j2].y : bi[j2].x));
                int kk = jj*8 + ((lane&3)<<1) + (e&1);
                int rt = (lane>>2) + ((e>>1)<<3);
                smu[gb[wn] + AFIDX(wm*4+i,kk>>3,(rt>>3)+((kk&4)?2:0)) + ((rt&7)*4+(kk&3))]
                    = rna(sv);
            }
        }
        __syncthreads();
        #pragma unroll
        for (int b=0;b<4;b++){
            int g = b*2 + r;
            #pragma unroll
            for (int ks=0;ks<4;ks++){
                u32 a[4];
                #pragma unroll
                for (int j=0;j<4;j++) a[j] = smu[gb[b] + AFIDX(w,ks,j) + lane];
                int ksg = g*4 + ks;
                #pragma unroll
                for (int n2=0;n2<4;n2++){
                    u64 bb = ((const u64*)(smu+F_WG))[(n2*32+ksg)*32+lane];
                    mma8(gacc[n2], a, (u32)bb, (u32)(bb>>32));
                }
            }
        }
    }

    // ---- V_mu mma + final gate*V_mu store ----
    float vm[3][4][4];
    #pragma unroll
    for(int c=0;c<3;c++)for(int n2=0;n2<4;n2++)for(int e=0;e<4;e++) vm[c][n2][e]=0.f;
    #pragma unroll
    for (int c=0;c<3;c++)
    #pragma unroll
    for (int ks=0;ks<4;ks++){
        u32 a[4];
        #pragma unroll
        for (int j=0;j<4;j++) a[j] = smu[F_VH + c*4096 + AFIDX(w,ks,j) + lane];
        #pragma unroll
        for (int n2=0;n2<4;n2++){
            u64 bb = ((const u64*)(smu+F_WMU))[(n2*4+ks)*32+lane];
            mma8(vm[c][n2], a, (u32)bb, (u32)(bb>>32));
        }
    }
    #pragma unroll
    for (int n2=0;n2<4;n2++)
    #pragma unroll
    for (int h2=0;h2<2;h2++){
        int e0 = h2*2;
        int m0 = n2*8 + ((lane&3)<<1);
        float g0 = sigm(gacc[n2][e0]   + smf[F_WGB+m0]);
        float g1 = sigm(gacc[n2][e0+1] + smf[F_WGB+m0+1]);
        int node = node0 + w*16 + (lane>>2) + h2*8;
        float* p = out + (size_t)N*256 + (size_t)node*96 + m0*3;
        float2 p0 = {g0*vm[0][n2][e0],   g0*vm[1][n2][e0]};
        float2 p1 = {g0*vm[2][n2][e0],   g1*vm[0][n2][e0+1]};
        float2 p2 = {g1*vm[1][n2][e0+1], g1*vm[2][n2][e0+1]};
        *(float2*)(p) = p0; *(float2*)(p+2) = p1; *(float2*)(p+4) = p2;
    }
}

extern "C" void kernel_launch(void* const* d_in, const int* in_sizes, int n_in,
                              void* d_out, int out_size) {
    const float* s   = (const float*)d_in[0];
    const float* V   = (const float*)d_in[1];
    const float* Wh  = (const float*)d_in[2];
    const float* Wmu = (const float*)d_in[3];
    const float* Wm  = (const float*)d_in[4];
    const float* Wmb = (const float*)d_in[5];
    const float* Wg  = (const float*)d_in[6];
    const float* Wgb = (const float*)d_in[7];
    float* out = (float*)d_out;
    const int N = in_sizes[0] / 256;

    cudaFuncSetAttribute(gvp_kernel, cudaFuncAttributeMaxDynamicSharedMemorySize, SMEM_BYTES);
    prep<<<(83968+255)/256, 256>>>(Wm, Wg, Wh, Wmu);
    gvp_kernel<<<N/128, TPB, SMEM_BYTES>>>(s, V, Wmb, Wgb, out, N);
}

// round 8
// speedup vs baseline: 3.8096x; 3.8096x over previous
#include <cuda_runtime.h>
#include <cstdint>

typedef uint32_t u32; typedef unsigned long long u64;
#define TPB 512

// ---- smem byte offsets ----
#define S_A0   0
#define S_A1   16384
#define S_B0   32768
#define S_B1   65536
#define S_SIG  0          // sigma frags 128KB (overlaps dead mainloop bufs)
#define S_VH   131072     // 3 x 16KB tf32 V_h frag tiles
#define S_BG   180224     // gate B stream 32KB
#define S_WMU  212992     // 4KB
#define S_WH   217088     // 4KB
#define S_BIAS 221184     // 1KB
#define S_WGB  222208     // 128B
#define SMEM_TOTAL 222336
// V component tiles (prologue only, dead before mainloop staging):
#define S_VT0  0
#define S_VT1  16384
#define S_VT2  65536

// Pre-rounded, quad-packed weights. Quad layout per 32-k chunk:
//   quad idx = (nt*2 + kh)*32 + lane ; 4 u32: j = (ks&1)*2 + i
//   value = W[n = nt*8 + lane/4][k = kh*16 + (j>>1)*8 + lane%4 + (j&1)*4]
__device__ u32 g_Bm[9*8192];
__device__ u32 g_Bg[8*1024];
__device__ u32 g_Bh[1024];
__device__ u32 g_Bmu[1024];

__device__ __forceinline__ u32 rna(float x){u32 u;asm("cvt.rna.tf32.f32 %0,%1;":"=r"(u):"f"(x));return u;}

__global__ void prep(const float* __restrict__ Wm, const float* __restrict__ Wg,
                     const float* __restrict__ Wh, const float* __restrict__ Wmu){
    int i = blockIdx.x*blockDim.x + threadIdx.x;
    if (i < 73728){
        int c=i>>13, r=i&8191, q=r>>2, j=r&3, lane=q&31, t2=q>>5, kh=t2&1, nt=t2>>1;
        g_Bm[i] = rna(Wm[(nt*8+(lane>>2))*288 + c*32 + kh*16 + (j>>1)*8 + (lane&3) + (j&1)*4]);
    } else if (i < 81920){
        int p=i-73728, c2=p>>10, r=p&1023, q=r>>2, j=r&3, lane=q&31, t2=q>>5, kh=t2&1, nt=t2>>1;
        g_Bg[p] = rna(Wg[(nt*8+(lane>>2))*256 + c2*32 + kh*16 + (j>>1)*8 + (lane&3) + (j&1)*4]);
    } else if (i < 82944){
        int p=i-81920, q=p>>2, j=p&3, lane=q&31, t2=q>>5, kh=t2&1, nt=t2>>1;
        g_Bh[p] = rna(Wh[(nt*8+(lane>>2))*32 + kh*16 + (j>>1)*8 + (lane&3) + (j&1)*4]);
    } else if (i < 83968){
        int p=i-82944, q=p>>2, j=p&3, lane=q&31, t2=q>>5, kh=t2&1, nt=t2>>1;
        g_Bmu[p] = rna(Wmu[(nt*8+(lane>>2))*32 + kh*16 + (j>>1)*8 + (lane&3) + (j&1)*4]);
    }
}

__device__ __forceinline__ void mma8(float* d, const u32* a, u32 b0, u32 b1){
    asm volatile("mma.sync.aligned.m16n8k8.row.col.f32.tf32.tf32.f32 "
        "{%0,%1,%2,%3},{%4,%5,%6,%7},{%8,%9},{%0,%1,%2,%3};"
        : "+f"(d[0]),"+f"(d[1]),"+f"(d[2]),"+f"(d[3])
        : "r"(a[0]),"r"(a[1]),"r"(a[2]),"r"(a[3]),"r"(b0),"r"(b1));
}
__device__ __forceinline__ u32 smem_u32(const void* p){
    u32 a;asm("{ .reg .u64 t; cvta.to.shared.u64 t,%1; cvt.u32.u64 %0,t; }":"=r"(a):"l"(p));return a;}
__device__ __forceinline__ void cpasync16(u32 d, const void* s){
    asm volatile("cp.async.cg.shared.global [%0], [%1], 16;"::"r"(d),"l"(s):"memory");}
#define CP_COMMIT asm volatile("cp.async.commit_group;":::"memory")
#define CP_WAIT(n) asm volatile("cp.async.wait_group %0;"::"n"(n):"memory")
#define LDS128(r, ad) asm volatile("ld.shared.v4.u32 {%0,%1,%2,%3},[%4];" \
  : "=r"((r)[0]),"=r"((r)[1]),"=r"((r)[2]),"=r"((r)[3]) : "r"(ad))
#define STS128(ad, r) asm volatile("st.shared.v4.u32 [%0],{%1,%2,%3,%4};" \
  :: "r"(ad),"r"((r)[0]),"r"((r)[1]),"r"((r)[2]),"r"((r)[3]) : "memory")
#define STS64(ad, x, y) asm volatile("st.shared.v2.u32 [%0],{%1,%2};" :: "r"(ad),"r"(x),"r"(y) : "memory")
__device__ __forceinline__ float sigm(float x){return 1.f/(1.f+__expf(-x));}

__global__ void __launch_bounds__(TPB,1) gvp_kernel(
    const float* __restrict__ s_g, const float* __restrict__ V_g,
    const float* __restrict__ Wmb, const float* __restrict__ Wgb,
    float* __restrict__ out, int N)
{
    extern __shared__ char smc[];
    const u32 smb = smem_u32(smc);
    const int t = threadIdx.x, lane = t&31, w = t>>5;
    const int wm = w>>3, wn = w&7;     // main GEMM: warp = 64 rows x 32 cols
    const int gm = w>>1, gn = w&1;     // V_h / gate / V_mu: warp = 16 rows x 16 cols
    const int r7 = lane>>2, c4 = lane&3;
    const int node0 = blockIdx.x*128;

    // ---- prologue ----
    if (t < 64) ((float4*)(smc+S_BIAS))[t] = ((const float4*)Wmb)[t];
    if (t >= 64 && t < 72) ((float4*)(smc+S_WGB))[t-64] = ((const float4*)Wgb)[t-64];
    if (t < 256) {
        ((float4*)(smc+S_WMU))[t] = ((const float4*)g_Bmu)[t];
        ((float4*)(smc+S_WH))[t]  = ((const float4*)g_Bh)[t];
    }
    #pragma unroll
    for (int q=0;q<4;q++)   // B chunk0 -> B0 (overlaps V_h phase)
        cpasync16(smb + S_B0 + (t+512*q)*16, g_Bm + (t+512*q)*4);
    CP_COMMIT;

    // V scatter into 3 component A-frag tiles
    const u32 vtOff[3] = {S_VT0, S_VT1, S_VT2};
    #pragma unroll
    for (int q=0;q<6;q++){
        int g = t + 512*q, node = g/24, jj = g - node*24;
        float4 v4 = ((const float4*)V_g)[(size_t)(node0+node)*24 + jj];
        float vv[4] = {v4.x, v4.y, v4.z, v4.w};
        int mt = node>>4, rt = node&15;
        #pragma unroll
        for (int e=0;e<4;e++){
            int f = jj*4+e, vi = f/3, comp = f - vi*3;
            int lp = (rt&7)*4 + (vi&3);
            int jq = ((rt>>3)&1) + ((vi&4)?2:0);
            *(u32*)(smc + vtOff[comp] + (((mt*4+(vi>>3))*32 + lp)*4 + jq)*4) = rna(vv[e]);
        }
    }
    // A chunk0 prefetch (frag-direct global loads)
    float ap[8];
    {
        #pragma unroll
        for (int h=0;h<2;h++){
            int u = t + 512*h, mt=u>>7, ks=(u>>5)&3, lq=u&31, r=lq>>2, cc=lq&3;
            const float* base = s_g + (size_t)(node0 + mt*16 + r)*256 + ks*8 + cc;
            ap[h*4+0]=base[0]; ap[h*4+1]=base[8*256]; ap[h*4+2]=base[4]; ap[h*4+3]=base[8*256+4];
        }
    }
    __syncthreads();

    // ---- V_h mma: warp (gm, gn) owns 16 rows x 2 n-tiles ----
    float vh[3][2][4];
    #pragma unroll
    for(int c=0;c<3;c++)for(int n2=0;n2<2;n2++)for(int e=0;e<4;e++) vh[c][n2][e]=0.f;
    #pragma unroll
    for (int c=0;c<3;c++)
    #pragma unroll
    for (int ks=0;ks<4;ks++){
        u32 a[4]; LDS128(a, smb + vtOff[c] + ((gm*4+ks)*32+lane)*16);
        #pragma unroll
        for (int n2=0;n2<2;n2++){
            u32 bq[4]; LDS128(bq, smb + S_WH + (((gn*2+n2)*2+(ks>>1))*32+lane)*16);
            mma8(vh[c][n2], a, bq[(ks&1)*2], bq[(ks&1)*2+1]);
        }
    }
    // norm -> sh regs (chunk-8 A) + V_h tf32 frag tiles
    u32 shq[8];
    #pragma unroll
    for (int n2=0;n2<2;n2++)
    #pragma unroll
    for (int e=0;e<4;e++){
        float x=vh[0][n2][e], y=vh[1][n2][e], z=vh[2][n2][e];
        shq[n2*4+e] = rna(fmaxf(sqrtf(x*x+y*y+z*z), 1e-4f));
        int h = (gn*2+n2)*8 + 2*c4 + (e&1);
        int lp = r7*4 + (h&3);
        int jq = ((e>>1)&1) + ((h&4)?2:0);
        u32 idx = (((gm*4+(h>>3))*32 + lp)*4 + jq)*4;
        *(u32*)(smc + S_VH         + idx) = rna(x);
        *(u32*)(smc + S_VH + 16384 + idx) = rna(y);
        *(u32*)(smc + S_VH + 32768 + idx) = rna(z);
    }
    __syncthreads();

    // ---- main GEMM: 9 chunks of K=32, double-buffered ----
    float acc[4][4][4];
    #pragma unroll
    for(int i=0;i<4;i++)for(int j=0;j<4;j++)for(int e=0;e<4;e++) acc[i][j][e]=0.f;

    for (int c=0;c<9;c++){
        int buf = c&1;
        u32 aOff = buf? S_A1:S_A0;
        u32 bRd = buf? S_B1:S_B0, bWr = buf? S_B0:S_B1;
        if (c<8){
            #pragma unroll
            for (int h=0;h<2;h++){
                u32 q4[4] = {rna(ap[h*4]),rna(ap[h*4+1]),rna(ap[h*4+2]),rna(ap[h*4+3])};
                STS128(smb + aOff + (t+512*h)*16, q4);
            }
        } else {
            #pragma unroll
            for (int n2=0;n2<2;n2++)
            #pragma unroll
            for (int e=0;e<4;e++){
                int h = (gn*2+n2)*8 + 2*c4 + (e&1);
                int lp = r7*4 + (h&3);
                int jq = ((e>>1)&1) + ((h&4)?2:0);
                *(u32*)(smc + aOff + (((gm*4+(h>>3))*32 + lp)*4 + jq)*4) = shq[n2*4+e];
            }
        }
        if (c<7){
            #pragma unroll
            for (int h=0;h<2;h++){
                int u = t + 512*h, mt=u>>7, ks=(u>>5)&3, lq=u&31, r=lq>>2, cc=lq&3;
                const float* base = s_g + (size_t)(node0 + mt*16 + r)*256 + (c+1)*32 + ks*8 + cc;
                ap[h*4+0]=base[0]; ap[h*4+1]=base[8*256]; ap[h*4+2]=base[4]; ap[h*4+3]=base[8*256+4];
            }
        }
        if (c<8){
            const u32* src = g_Bm + (c+1)*8192;
            #pragma unroll
            for (int q=0;q<4;q++)
                cpasync16(smb + bWr + (t+512*q)*16, src + (t+512*q)*4);
            CP_COMMIT; CP_WAIT(1);
        } else { CP_WAIT(0); }
        __syncthreads();

        #pragma unroll
        for (int kh=0;kh<2;kh++){
            u32 b[4][4];
            #pragma unroll
            for (int j2=0;j2<4;j2++)
                LDS128(b[j2], smb + bRd + (((wn*4+j2)*2+kh)*32+lane)*16);
            #pragma unroll
            for (int ks2=0;ks2<2;ks2++){
                int ks = kh*2+ks2;
                u32 a[4][4];
                #pragma unroll
                for (int i=0;i<4;i++)
                    LDS128(a[i], smb + aOff + (((wm*4+i)*4+ks)*32+lane)*16);
                #pragma unroll
                for (int i=0;i<4;i++)
                    #pragma unroll
                    for (int j2=0;j2<4;j2++)
                        mma8(acc[i][j2], a[i], b[j2][ks2*2], b[j2][ks2*2+1]);
            }
        }
        __syncthreads();
    }

    // ---- epilogue: relu store + sigma frags; gate & V_mu mma; final store ----
    #pragma unroll
    for (int q=0;q<4;q++)   // stream gate weights
        cpasync16(smb + S_BG + (t+512*q)*16, g_Bg + (t+512*q)*4);
    CP_COMMIT;

    float2 bi[4];
    #pragma unroll
    for (int j2=0;j2<4;j2++)
        bi[j2] = *(const float2*)(smc + S_BIAS + (wn*32 + j2*8 + c4*2)*4);

    #pragma unroll
    for (int i=0;i<4;i++)
    #pragma unroll
    for (int j2=0;j2<4;j2++){
        int C = wn*32 + j2*8 + c4*2;
        size_t R = (size_t)node0 + wm*64 + i*16 + r7;
        float m0=acc[i][j2][0]+bi[j2].x, m1=acc[i][j2][1]+bi[j2].y;
        float m2=acc[i][j2][2]+bi[j2].x, m3=acc[i][j2][3]+bi[j2].y;
        float2 o0 = {fmaxf(m0,0.f), fmaxf(m1,0.f)};
        float2 o1 = {fmaxf(m2,0.f), fmaxf(m3,0.f)};
        *(float2*)(out + R*256 + C) = o0;
        *(float2*)(out + (R+8)*256 + C) = o1;
        u32 s0=rna(sigm(m0)), s1=rna(sigm(m1)), s2=rna(sigm(m2)), s3=rna(sigm(m3));
        int kseq = C>>3, c8 = C&7, mt = wm*4+i;
        u32 a0 = smb + S_SIG + ((u32)((mt*32+kseq)*32 + r7*4 + (c8&3)))*16 + ((c8&4)?8:0);
        STS64(a0, s0, s2);
        int c8b = c8+1;
        u32 a1 = smb + S_SIG + ((u32)((mt*32+kseq)*32 + r7*4 + (c8b&3)))*16 + ((c8b&4)?8:0);
        STS64(a1, s1, s3);
    }
    CP_WAIT(0);
    __syncthreads();

    // gate GEMM: [128 x 32] = sigma[128 x 256] @ Wg^T, warp = (gm, gn)
    float gacc[2][4];
    #pragma unroll
    for(int n2=0;n2<2;n2++)for(int e=0;e<4;e++) gacc[n2][e]=0.f;
    for (int kc=0;kc<8;kc++){
        #pragma unroll
        for (int kh=0;kh<2;kh++){
            u32 b[2][4];
            #pragma unroll
            for (int n2=0;n2<2;n2++)
                LDS128(b[n2], smb + S_BG + kc*4096 + (((gn*2+n2)*2+kh)*32+lane)*16);
            #pragma unroll
            for (int ks2=0;ks2<2;ks2++){
                int kseq = kc*4 + kh*2 + ks2;
                u32 a[4]; LDS128(a, smb + S_SIG + ((gm*32+kseq)*32+lane)*16);
                #pragma unroll
                for (int n2=0;n2<2;n2++)
                    mma8(gacc[n2], a, b[n2][ks2*2], b[n2][ks2*2+1]);
            }
        }
    }
    // V_mu mma from VH frag tiles
    float vm[3][2][4];
    #pragma unroll
    for(int c=0;c<3;c++)for(int n2=0;n2<2;n2++)for(int e=0;e<4;e++) vm[c][n2][e]=0.f;
    u32 bmu[2][2][4];
    #pragma unroll
    for (int n2=0;n2<2;n2++)
    #pragma unroll
    for (int kh=0;kh<2;kh++)
        LDS128(bmu[n2][kh], smb + S_WMU + (((gn*2+n2)*2+kh)*32+lane)*16);
    #pragma unroll
    for (int c3=0;c3<3;c3++)
    #pragma unroll
    for (int ks=0;ks<4;ks++){
        u32 a[4]; LDS128(a, smb + S_VH + c3*16384 + ((gm*4+ks)*32+lane)*16);
        #pragma unroll
        for (int n2=0;n2<2;n2++)
            mma8(vm[c3][n2], a, bmu[n2][ks>>1][(ks&1)*2], bmu[n2][ks>>1][(ks&1)*2+1]);
    }
    // final: V_dash = sigmoid(gate logits + b) * V_mu
    #pragma unroll
    for (int n2=0;n2<2;n2++){
        int m0c = (gn*2+n2)*8 + c4*2;
        float wg0 = *(const float*)(smc + S_WGB + m0c*4);
        float wg1 = *(const float*)(smc + S_WGB + (m0c+1)*4);
        #pragma unroll
        for (int h2=0;h2<2;h2++){
            int e0 = h2*2;
            float g0 = sigm(gacc[n2][e0]   + wg0);
            float g1 = sigm(gacc[n2][e0+1] + wg1);
            size_t node = (size_t)node0 + gm*16 + r7 + h2*8;
            float* p = out + (size_t)N*256 + node*96 + m0c*3;
            float2 q0 = {g0*vm[0][n2][e0],   g0*vm[1][n2][e0]};
            float2 q1 = {g0*vm[2][n2][e0],   g1*vm[0][n2][e0+1]};
            float2 q2 = {g1*vm[1][n2][e0+1], g1*vm[2][n2][e0+1]};
            *(float2*)p = q0; *(float2*)(p+2) = q1; *(float2*)(p+4) = q2;
        }
    }
}

extern "C" void kernel_launch(void* const* d_in, const int* in_sizes, int n_in,
                              void* d_out, int out_size) {
    const float* s   = (const float*)d_in[0];
    const float* V   = (const float*)d_in[1];
    const float* Wh  = (const float*)d_in[2];
    const float* Wmu = (const float*)d_in[3];
    const float* Wm  = (const float*)d_in[4];
    const float* Wmb = (const float*)d_in[5];
    const float* Wg  = (const float*)d_in[6];
    const float* Wgb = (const float*)d_in[7];
    float* out = (float*)d_out;
    const int N = in_sizes[0] / 256;

    cudaFuncSetAttribute(gvp_kernel, cudaFuncAttributeMaxDynamicSharedMemorySize, SMEM_TOTAL);
    prep<<<(83968+255)/256, 256>>>(Wm, Wg, Wh, Wmu);
    gvp_kernel<<<N/128, TPB, SMEM_TOTAL>>>(s, V, Wmb, Wgb, out, N);
}